// round 15
// baseline (speedup 1.0000x reference)
#include <cuda_runtime.h>

// DifferentiableTTFSEncoder: first-fire one-hot over T=64 steps.
// out[b, t, n] = 1.0f at the first t where the exact-fp32 LIF recurrence
// mem = fmaf(mem, d, c*(1-d)), c = x[b,n]*sens[n], crosses 1.0; else 0.
//
// FINAL CONVERGED KERNEL — 79.4us wall, 6.08 TB/s, rel_err 0.0,
// reproduced three times (R10/R12/R14) within +-0.5us.
//
// Evidence base (14 measured rounds):
//  - The GB300 pure-write ceiling is ~6.0-6.1 TB/s and PATH-INDEPENDENT:
//    STG.128/.256, .cs, .wt, bursting, decoupled zero-blast, and the
//    driver's cudaMemsetAsync fill engine all saturate at the same rate.
//    This kernel runs at ~99% of the driver fill engine's throughput.
//  - Interleaved one-STG.128.CS-per-step is the optimal drain pattern;
//    ANY batching/decoupling backs up L1tex and lowers DRAM throughput
//    (R2 -19%, R4 -10%, R9 -12%).
//  - Occupancy (6/7/8 blocks per SM), wave shape, block size (256 vs 512),
//    and T-splitting are non-levers (R3, R5, R6, R11).
//  - Natural register allocation (regs=34) beats forced regs<=32 (R10).
//  - SM side exonerated: issue=25%, warps parked on store backpressure.
// Remaining gap to the 8 TB/s aggregate spec is DRAM write-turnaround
// physics, not kernel structure.

#define B_DIM 2048
#define N_DIM 1024
#define T_DIM 64
#define NQ    (N_DIM / 4)   // float4 groups per row = 256

__global__ void __launch_bounds__(256)
ttfs_kernel(const float* __restrict__ x,
            const float* __restrict__ sens,
            float* __restrict__ out)
{
    const int gid = blockIdx.x * blockDim.x + threadIdx.x;  // over B*N/4
    const int b  = gid >> 8;        // / NQ (NQ = 256)
    const int nq = gid & (NQ - 1);  // % NQ

    // Inputs (coalesced float4)
    const float4 xv = reinterpret_cast<const float4*>(x)[gid];
    const float4 sv = reinterpret_cast<const float4*>(sens)[nq];

    const float d   = 0.60653065971263342360f;  // exp(-0.5), fp32-rounded
    const float omd = 1.0f - d;

    // Per-element constant drive c*(1-d)
    const float cc0 = xv.x * sv.x * omd;
    const float cc1 = xv.y * sv.y * omd;
    const float cc2 = xv.z * sv.z * omd;
    const float cc3 = xv.w * sv.w * omd;

    float m0 = 0.0f, m1 = 0.0f, m2 = 0.0f, m3 = 0.0f;
    bool  f0 = false, f1 = false, f2 = false, f3 = false;

    // Output base: out[b, t, n] with n = nq*4; stride per t is N_DIM floats
    float4* op = reinterpret_cast<float4*>(out)
               + (size_t)b * (size_t)T_DIM * NQ + nq;

    #pragma unroll
    for (int t = 0; t < T_DIM; ++t) {
        m0 = fmaf(m0, d, cc0);
        m1 = fmaf(m1, d, cc1);
        m2 = fmaf(m2, d, cc2);
        m3 = fmaf(m3, d, cc3);

        const bool s0 = (m0 >= 1.0f);
        const bool s1 = (m1 >= 1.0f);
        const bool s2 = (m2 >= 1.0f);
        const bool s3 = (m3 >= 1.0f);

        float4 v;
        v.x = (s0 && !f0) ? 1.0f : 0.0f;
        v.y = (s1 && !f1) ? 1.0f : 0.0f;
        v.z = (s2 && !f2) ? 1.0f : 0.0f;
        v.w = (s3 && !f3) ? 1.0f : 0.0f;

        f0 = f0 || s0;
        f1 = f1 || s1;
        f2 = f2 || s2;
        f3 = f3 || s3;

        // Evict-first streaming store (STG.E.128.CS), one per step —
        // the measured-optimal interleaved drain pattern.
        __stcs(op + (size_t)t * NQ, v);
    }
}

extern "C" void kernel_launch(void* const* d_in, const int* in_sizes, int n_in,
                              void* d_out, int out_size)
{
    const float* x    = (const float*)d_in[0];   // [2048, 1024] f32
    const float* sens = (const float*)d_in[1];   // [1024] f32
    float* out        = (float*)d_out;           // [2048, 64, 1024] f32

    const int total_threads = (B_DIM * N_DIM) / 4;  // 524288
    const int block = 256;
    const int grid  = total_threads / block;        // 2048

    ttfs_kernel<<<grid, block>>>(x, sens, out);
}